// round 11
// baseline (speedup 1.0000x reference)
#include <cuda_runtime.h>
#include <cuda_bf16.h>

// Shapes (compile-time constants)
#define NB   512           // sequence length
#define DD   256           // model dim
#define HH   8             // heads
#define HID  682           // swiglu hidden
#define QKVD 768

typedef unsigned long long u64;

// ---------------- device scratch ----------------
__device__ float g_xn[NB * DD];
__device__ float g_qkv[NB * QKVD];
__device__ float2 g_PKT[DD * NB];    // (.x = K^T[k][j], .y = 0.5*Pb^T[k][j])
__device__ float g_Pb[NB * DD];      // 0.5 * Pb
__device__ float g_Pv[NB * DD];      // 0.5 * Pv
__device__ float g_rv2T[DD * DD];    // rv2 transposed [k][d]
__device__ float g_w[NB * NB * HH];  // logits -> softmax weights [i][j*HH+h]  (8MB)
__device__ float g_Tp[NB * 2 * HH * DD];   // partial T (8MB)
__device__ float g_c1p[NB * 2 * DD];       // partial c1 (1MB)
__device__ float g_y[NB * DD];
__device__ float g_xn2[NB * DD];
__device__ float g_h1[NB * HID];

// ---- packed f32x2 helpers (sm_100+) ----
__device__ __forceinline__ u64 pk2(float lo, float hi) {
    u64 r;
    asm("mov.b64 %0, {%1, %2};" : "=l"(r) : "f"(lo), "f"(hi));
    return r;
}
__device__ __forceinline__ float2 up2(u64 v) {
    float2 f;
    asm("mov.b64 {%0, %1}, %2;" : "=f"(f.x), "=f"(f.y) : "l"(v));
    return f;
}
__device__ __forceinline__ u64 fma2(u64 a, u64 b, u64 c) {
    u64 d;
    asm("fma.rn.f32x2 %0, %1, %2, %3;" : "=l"(d) : "l"(a), "l"(b), "l"(c));
    return d;
}
__device__ __forceinline__ u64 add2(u64 a, u64 b) {
    u64 d;
    asm("add.rn.f32x2 %0, %1, %2;" : "=l"(d) : "l"(a), "l"(b));
    return d;
}

// silu from the HALF-difference s = 0.5*(a-b): silu(a-b) = s*tanh(s)+s
__device__ __forceinline__ float silu_h(float s) {
    float t;
    asm("tanh.approx.f32 %0, %1;" : "=f"(t) : "f"(s));
    return fmaf(s, t, s);
}
// accurate silu for the (cold) FFN epilogue
__device__ __forceinline__ float silu_acc(float v) {
    return v / (1.0f + __expf(-v));
}

// ---------------- LayerNorm: one block per row, 256 threads ----------------
__global__ __launch_bounds__(256) void ln_kernel(const float* __restrict__ x,
                                                 const float* __restrict__ w,
                                                 const float* __restrict__ b,
                                                 float* __restrict__ out) {
    int row = blockIdx.x, t = threadIdx.x;
    float v = x[row * DD + t];
    float s = v, q = v * v;
#pragma unroll
    for (int o = 16; o; o >>= 1) {
        s += __shfl_xor_sync(0xffffffff, s, o);
        q += __shfl_xor_sync(0xffffffff, q, o);
    }
    __shared__ float ss[8], sq[8];
    int warp = t >> 5, lane = t & 31;
    if (lane == 0) { ss[warp] = s; sq[warp] = q; }
    __syncthreads();
    s = 0.f; q = 0.f;
#pragma unroll
    for (int k = 0; k < 8; k++) { s += ss[k]; q += sq[k]; }
    float mean = s * (1.0f / DD);
    float var = q * (1.0f / DD) - mean * mean;
    out[row * DD + t] = (v - mean) * rsqrtf(var + 1e-5f) * w[t] + b[t];
}

// ---------------- coords projection (all outputs HALF-scaled) ----------------
__global__ __launch_bounds__(256) void proj3_kernel(const float* __restrict__ coords,
                                                    const float* __restrict__ rb1,
                                                    const float* __restrict__ rv1,
                                                    float* __restrict__ Pb,
                                                    float2* __restrict__ PKT,
                                                    float* __restrict__ Pv) {
    int i = blockIdx.x, k = threadIdx.x;
    float c0 = coords[i * 3 + 0], c1 = coords[i * 3 + 1], c2 = coords[i * 3 + 2];
    float pb = rb1[k * 3 + 0] * c0 + rb1[k * 3 + 1] * c1 + rb1[k * 3 + 2] * c2;
    float pv = rv1[k * 3 + 0] * c0 + rv1[k * 3 + 1] * c1 + rv1[k * 3 + 2] * c2;
    Pb[i * DD + k] = 0.5f * pb;
    PKT[k * NB + i].y = 0.5f * pb;
    Pv[i * DD + k] = 0.5f * pv;
}

// ---------------- generic 32x32-tiled transpose ----------------
__global__ __launch_bounds__(256) void transpose_kernel(const float* __restrict__ in,
                                                        float* __restrict__ out,
                                                        int R, int C, int ldin, int off) {
    __shared__ float tile[32][33];
    int c0 = blockIdx.x * 32, r0 = blockIdx.y * 32;
    int tx = threadIdx.x, ty = threadIdx.y;  // 32 x 8
#pragma unroll
    for (int s = 0; s < 32; s += 8)
        tile[ty + s][tx] = in[(r0 + ty + s) * ldin + off + c0 + tx];
    __syncthreads();
#pragma unroll
    for (int s = 0; s < 32; s += 8)
        out[(c0 + ty + s) * R + r0 + tx] = tile[tx][ty + s];
}

// ---------------- GEMM: C = A @ W^T (+bias), 32x64 tile; optional K^T side-write ----
__global__ __launch_bounds__(256, 2) void gemm_t(const float* __restrict__ A,
                                                 const float* __restrict__ W,
                                                 const float* __restrict__ bias,
                                                 float2* __restrict__ PKT,  // nullable
                                                 float* __restrict__ C,
                                                 int M, int N, int K) {
    __shared__ __align__(16) u64 As[32][34];     // [k][m] duplicated
    __shared__ __align__(16) float Ws[32][68];   // [k][n]
    int tid = threadIdx.x;
    int tx = tid & 15, ty = tid >> 4;            // tx -> n (4 cols), ty -> m (2 rows)
    int row0 = blockIdx.y * 32, col0 = blockIdx.x * 64;
    u64 acc[2][2] = {};
    for (int k0 = 0; k0 < K; k0 += 32) {
#pragma unroll
        for (int l = 0; l < 4; l++) {            // A: 32x32
            int idx = l * 256 + tid;
            int m = idx >> 5, k = idx & 31;
            int gk = k0 + k, ar = row0 + m;
            float v = (ar < M && gk < K) ? A[ar * K + gk] : 0.f;
            As[k][m] = pk2(v, v);
        }
#pragma unroll
        for (int l = 0; l < 8; l++) {            // W: 64x32
            int idx = l * 256 + tid;
            int m = idx >> 5, k = idx & 31;
            int gk = k0 + k, wr = col0 + m;
            Ws[k][m] = (wr < N && gk < K) ? W[wr * K + gk] : 0.f;
        }
        __syncthreads();
#pragma unroll
        for (int kk = 0; kk < 32; kk++) {
            ulonglong2 Av = *(const ulonglong2*)&As[kk][ty * 2];
            ulonglong2 Bv = *(const ulonglong2*)&Ws[kk][tx * 4];
            acc[0][0] = fma2(Av.x, Bv.x, acc[0][0]);
            acc[0][1] = fma2(Av.x, Bv.y, acc[0][1]);
            acc[1][0] = fma2(Av.y, Bv.x, acc[1][0]);
            acc[1][1] = fma2(Av.y, Bv.y, acc[1][1]);
        }
        __syncthreads();
    }
#pragma unroll
    for (int r = 0; r < 2; r++) {
        int m = row0 + ty * 2 + r;
        if (m >= M) continue;
#pragma unroll
        for (int c2 = 0; c2 < 2; c2++) {
            float2 v = up2(acc[r][c2]);
            int n0 = col0 + tx * 4 + c2 * 2;
            if (n0 < N) {
                float o = v.x + (bias ? bias[n0] : 0.f);
                C[m * N + n0] = o;
                if (PKT && n0 >= DD && n0 < 2 * DD) PKT[(n0 - DD) * NB + m].x = o;
            }
            if (n0 + 1 < N) {
                float o = v.y + (bias ? bias[n0 + 1] : 0.f);
                C[m * N + n0 + 1] = o;
                if (PKT && n0 + 1 >= DD && n0 + 1 < 2 * DD) PKT[(n0 + 1 - DD) * NB + m].x = o;
            }
        }
    }
}

// ---------------- GEMM 32x32 tile (better grid fill for small N) ----------------
__global__ __launch_bounds__(256, 3) void gemm_t32(const float* __restrict__ A,
                                                   const float* __restrict__ W,
                                                   const float* __restrict__ bias,
                                                   const float* __restrict__ residual,
                                                   float* __restrict__ C,
                                                   int M, int N, int K) {
    __shared__ __align__(16) u64 As[32][34];     // [k][m] duplicated
    __shared__ __align__(16) float Ws[32][36];   // [k][n]
    int tid = threadIdx.x;
    int tx = tid & 7, ty = tid >> 3;             // tx -> n (4 cols), ty -> m (1 row)
    int row0 = blockIdx.y * 32, col0 = blockIdx.x * 32;
    u64 acc[2] = {};
    for (int k0 = 0; k0 < K; k0 += 32) {
#pragma unroll
        for (int l = 0; l < 4; l++) {
            int idx = l * 256 + tid;
            int m = idx >> 5, k = idx & 31;
            int gk = k0 + k;
            int ar = row0 + m, wr = col0 + m;
            float va = (ar < M && gk < K) ? A[ar * K + gk] : 0.f;
            As[k][m] = pk2(va, va);
            Ws[k][m] = (wr < N && gk < K) ? W[wr * K + gk] : 0.f;
        }
        __syncthreads();
#pragma unroll
        for (int kk = 0; kk < 32; kk++) {
            u64 Av = As[kk][ty];
            ulonglong2 Bv = *(const ulonglong2*)&Ws[kk][tx * 4];
            acc[0] = fma2(Av, Bv.x, acc[0]);
            acc[1] = fma2(Av, Bv.y, acc[1]);
        }
        __syncthreads();
    }
    int m = row0 + ty;
    if (m < M) {
#pragma unroll
        for (int c2 = 0; c2 < 2; c2++) {
            float2 v = up2(acc[c2]);
            int n0 = col0 + tx * 4 + c2 * 2;
            if (n0 < N) {
                float o = v.x;
                if (bias) o += bias[n0];
                if (residual) o += residual[m * N + n0];
                C[m * N + n0] = o;
            }
            if (n0 + 1 < N) {
                float o = v.y;
                if (bias) o += bias[n0 + 1];
                if (residual) o += residual[m * N + n0 + 1];
                C[m * N + n0 + 1] = o;
            }
        }
    }
}

// ---------------- fused SwiGLU dual-GEMM, 32x64 tile ----------------
__global__ __launch_bounds__(256, 2) void gemm_swiglu(const float* __restrict__ A,
                                                      const float* __restrict__ W1,
                                                      const float* __restrict__ b1,
                                                      const float* __restrict__ W2,
                                                      const float* __restrict__ b2,
                                                      float* __restrict__ Hout,
                                                      int M, int N, int K) {
    __shared__ __align__(16) u64 As[32][34];
    __shared__ __align__(16) float W1s[32][68];
    __shared__ __align__(16) float W2s[32][68];
    int tid = threadIdx.x;
    int tx = tid & 15, ty = tid >> 4;
    int row0 = blockIdx.y * 32, col0 = blockIdx.x * 64;
    u64 acc1[2][2] = {};
    u64 acc2[2][2] = {};
    for (int k0 = 0; k0 < K; k0 += 32) {
#pragma unroll
        for (int l = 0; l < 4; l++) {
            int idx = l * 256 + tid;
            int m = idx >> 5, k = idx & 31;
            int gk = k0 + k, ar = row0 + m;
            float v = (ar < M && gk < K) ? A[ar * K + gk] : 0.f;
            As[k][m] = pk2(v, v);
        }
#pragma unroll
        for (int l = 0; l < 8; l++) {
            int idx = l * 256 + tid;
            int m = idx >> 5, k = idx & 31;
            int gk = k0 + k, wr = col0 + m;
            W1s[k][m] = (wr < N && gk < K) ? W1[wr * K + gk] : 0.f;
            W2s[k][m] = (wr < N && gk < K) ? W2[wr * K + gk] : 0.f;
        }
        __syncthreads();
#pragma unroll
        for (int kk = 0; kk < 32; kk++) {
            ulonglong2 Av = *(const ulonglong2*)&As[kk][ty * 2];
            ulonglong2 Bv = *(const ulonglong2*)&W1s[kk][tx * 4];
            ulonglong2 Cv = *(const ulonglong2*)&W2s[kk][tx * 4];
            acc1[0][0] = fma2(Av.x, Bv.x, acc1[0][0]);
            acc1[0][1] = fma2(Av.x, Bv.y, acc1[0][1]);
            acc1[1][0] = fma2(Av.y, Bv.x, acc1[1][0]);
            acc1[1][1] = fma2(Av.y, Bv.y, acc1[1][1]);
            acc2[0][0] = fma2(Av.x, Cv.x, acc2[0][0]);
            acc2[0][1] = fma2(Av.x, Cv.y, acc2[0][1]);
            acc2[1][0] = fma2(Av.y, Cv.x, acc2[1][0]);
            acc2[1][1] = fma2(Av.y, Cv.y, acc2[1][1]);
        }
        __syncthreads();
    }
#pragma unroll
    for (int r = 0; r < 2; r++) {
        int m = row0 + ty * 2 + r;
        if (m >= M) continue;
#pragma unroll
        for (int c2 = 0; c2 < 2; c2++) {
            float2 v1 = up2(acc1[r][c2]);
            float2 v2 = up2(acc2[r][c2]);
            int n0 = col0 + tx * 4 + c2 * 2;
            if (n0 < N)
                Hout[m * N + n0] = silu_acc(v1.x + b1[n0]) * (v2.x + b2[n0]);
            if (n0 + 1 < N)
                Hout[m * N + n0 + 1] = silu_acc(v1.y + b1[n0 + 1]) * (v2.y + b2[n0 + 1]);
        }
    }
}

// ---------------- attention 1a: raw logits, j-PAIR per thread ----------------
// grid (NB/2 pairs, 2 j-halves), 128 threads; thread t owns j-pair (jbase+2t, +1),
// both queries. FFMA2 packed over (j0, j1); rb2 pre-duplicated in smem.
__global__ __launch_bounds__(128, 6) void attn_logits(
    const float* __restrict__ qkv, const float2* __restrict__ PKT,
    const float* __restrict__ Pb, const float* __restrict__ rb1_b,
    const float* __restrict__ rb2_w, const float* __restrict__ rb2_b,
    float* __restrict__ gw_all) {
    const int i0 = blockIdx.x * 2;
    const int jbase = blockIdx.y * 256;
    const int t = threadIdx.x;          // 0..127
    const int j0 = jbase + 2 * t;

    __shared__ __align__(16) float4 sm_qpq[DD];     // (q0, hpb0, q1, hpb1)  4KB
    __shared__ __align__(16) u64 sm_rb2d[DD * HH];  // dup(rb2[h][k])       16KB

#pragma unroll
    for (int l = 0; l < 2; l++) {
        int k = l * 128 + t;
        float hb = 0.5f * rb1_b[k];
        sm_qpq[k] = make_float4(qkv[i0 * QKVD + k], Pb[i0 * DD + k] + hb,
                                qkv[(i0 + 1) * QKVD + k], Pb[(i0 + 1) * DD + k] + hb);
    }
#pragma unroll
    for (int h = 0; h < HH; h++)
#pragma unroll
        for (int l = 0; l < 2; l++) {
            int k = l * 128 + t;
            float r = rb2_w[h * DD + k];
            sm_rb2d[k * HH + h] = pk2(r, r);
        }
    __syncthreads();

    u64 bias[2][HH] = {};   // [q][h], packed over (j0, j1)
    const float sc = 0.17677669529663687f;
    const u64 scp = pk2(sc, sc);

#pragma unroll
    for (int h = 0; h < HH; h++) {
        u64 qk0 = 0ull, qk1 = 0ull;     // per-head q.k, packed over (j0, j1)
#pragma unroll 4
        for (int kk = 0; kk < 32; kk++) {
            int k = h * 32 + kk;
            float4 pkv = *(const float4*)(PKT + k * NB + j0);
            // pkv = (K[j0], hPb[j0], K[j1], hPb[j1])
            u64 kvp = pk2(pkv.x, pkv.z);
            float4 qq = sm_qpq[k];
            const u64* rd = sm_rb2d + k * HH;
            ulonglong2 rA = *(const ulonglong2*)(rd);
            ulonglong2 rB = *(const ulonglong2*)(rd + 2);
            ulonglong2 rC = *(const ulonglong2*)(rd + 4);
            ulonglong2 rD = *(const ulonglong2*)(rd + 6);
            // q0
            qk0 = fma2(pk2(qq.x, qq.x), kvp, qk0);
            {
                float ua = silu_h(qq.y - pkv.y);
                float ub = silu_h(qq.y - pkv.w);
                u64 up = pk2(ua, ub);
                bias[0][0] = fma2(up, rA.x, bias[0][0]);
                bias[0][1] = fma2(up, rA.y, bias[0][1]);
                bias[0][2] = fma2(up, rB.x, bias[0][2]);
                bias[0][3] = fma2(up, rB.y, bias[0][3]);
                bias[0][4] = fma2(up, rC.x, bias[0][4]);
                bias[0][5] = fma2(up, rC.y, bias[0][5]);
                bias[0][6] = fma2(up, rD.x, bias[0][6]);
                bias[0][7] = fma2(up, rD.y, bias[0][7]);
            }
            // q1
            qk1 = fma2(pk2(qq.z, qq.z), kvp, qk1);
            {
                float ua = silu_h(qq.w - pkv.y);
                float ub = silu_h(qq.w - pkv.w);
                u64 up = pk2(ua, ub);
                bias[1][0] = fma2(up, rA.x, bias[1][0]);
                bias[1][1] = fma2(up, rA.y, bias[1][1]);
                bias[1][2] = fma2(up, rB.x, bias[1][2]);
                bias[1][3] = fma2(up, rB.y, bias[1][3]);
                bias[1][4] = fma2(up, rC.x, bias[1][4]);
                bias[1][5] = fma2(up, rC.y, bias[1][5]);
                bias[1][6] = fma2(up, rD.x, bias[1][6]);
                bias[1][7] = fma2(up, rD.y, bias[1][7]);
            }
        }
        bias[0][h] = fma2(qk0, scp, bias[0][h]);
        bias[1][h] = fma2(qk1, scp, bias[1][h]);
    }

    // write raw logits: per (q, jslot) 8 heads as 2 float4 stores
#pragma unroll
    for (int q = 0; q < 2; q++) {
        float* wbase = gw_all + (i0 + q) * NB * HH + j0 * HH;
        float2 b0 = up2(bias[q][0]), b1 = up2(bias[q][1]);
        float2 b2 = up2(bias[q][2]), b3 = up2(bias[q][3]);
        float2 b4 = up2(bias[q][4]), b5 = up2(bias[q][5]);
        float2 b6 = up2(bias[q][6]), b7 = up2(bias[q][7]);
        float r0 = rb2_b[0], r1 = rb2_b[1], r2 = rb2_b[2], r3 = rb2_b[3];
        float r4 = rb2_b[4], r5 = rb2_b[5], r6 = rb2_b[6], r7 = rb2_b[7];
        *(float4*)(wbase + 0) = make_float4(b0.x + r0, b1.x + r1, b2.x + r2, b3.x + r3);
        *(float4*)(wbase + 4) = make_float4(b4.x + r4, b5.x + r5, b6.x + r6, b7.x + r7);
        *(float4*)(wbase + HH + 0) = make_float4(b0.y + r0, b1.y + r1, b2.y + r2, b3.y + r3);
        *(float4*)(wbase + HH + 4) = make_float4(b4.y + r4, b5.y + r5, b6.y + r6, b7.y + r7);
    }
}

// ---------------- attention 1b: softmax in place over j, per (query, head) -----------
__global__ __launch_bounds__(256, 4) void softmax_kernel(float* __restrict__ gw_all) {
    const int i = blockIdx.x;
    const int t = threadIdx.x;
    __shared__ float sw[NB * 9];   // padded [j][9] for conflict-free per-head access

    float4* gw4 = (float4*)(gw_all + i * NB * HH);
#pragma unroll
    for (int l = 0; l < 4; l++) {
        int idx = l * 256 + t;              // 1024 float4
        float4 v = gw4[idx];
        int jj = idx >> 1, half = (idx & 1) * 4;
        sw[jj * 9 + half + 0] = v.x;
        sw[jj * 9 + half + 1] = v.y;
        sw[jj * 9 + half + 2] = v.z;
        sw[jj * 9 + half + 3] = v.w;
    }
    __syncthreads();
    {
        int h = t >> 5, lane = t & 31;
        float m = -1e30f;
        for (int jj = lane; jj < NB; jj += 32) m = fmaxf(m, sw[jj * 9 + h]);
#pragma unroll
        for (int o = 16; o; o >>= 1) m = fmaxf(m, __shfl_xor_sync(0xffffffff, m, o));
        float s = 0.f;
        for (int jj = lane; jj < NB; jj += 32) {
            float e = __expf(sw[jj * 9 + h] - m);
            sw[jj * 9 + h] = e;
            s += e;
        }
#pragma unroll
        for (int o = 16; o; o >>= 1) s += __shfl_xor_sync(0xffffffff, s, o);
        float inv = 1.0f / s;
        for (int jj = lane; jj < NB; jj += 32) sw[jj * 9 + h] *= inv;
    }
    __syncthreads();
#pragma unroll
    for (int l = 0; l < 4; l++) {
        int idx = l * 256 + t;
        int jj = idx >> 1, half = (idx & 1) * 4;
        float4 v;
        v.x = sw[jj * 9 + half + 0];
        v.y = sw[jj * 9 + half + 1];
        v.z = sw[jj * 9 + half + 2];
        v.w = sw[jj * 9 + half + 3];
        gw4[idx] = v;
    }
}

// ---------------- attention 2a: partial T + partial c1, split over j halves ---------
__global__ __launch_bounds__(256, 4) void attn_ctx(
    const float* __restrict__ qkv, const float* __restrict__ Pv,
    const float* __restrict__ rv1_b, const float* __restrict__ gw_all,
    float* __restrict__ Tp, float* __restrict__ c1p) {
    const int pair = blockIdx.x;
    const int jh = blockIdx.y;
    const int i0 = pair * 2;
    const int jbase = jh * 256;
    const int t = threadIdx.x;

    __shared__ __align__(16) float sm_gw[2][256 * HH];  // staged weights (j half), 16KB

    {
        const float4* s0 = (const float4*)(gw_all + i0 * NB * HH + jbase * HH);
        const float4* s1 = (const float4*)(gw_all + (i0 + 1) * NB * HH + jbase * HH);
        float4* d0 = (float4*)sm_gw[0];
        float4* d1 = (float4*)sm_gw[1];
#pragma unroll
        for (int l = 0; l < 2; l++) {
            int idx = l * 256 + t;
            d0[idx] = s0[idx];
            d1[idx] = s1[idx];
        }
    }
    __syncthreads();

    const float* gw0 = sm_gw[0];
    const float* gw1 = sm_gw[1];
    const int h = t >> 5;
    float c1a = 0.f, c1b = 0.f;

    float pvb = 0.5f * rv1_b[t];
    float pvq0 = Pv[i0 * DD + t] + pvb;
    float pvq1 = Pv[(i0 + 1) * DD + t] + pvb;
    const float* Vp = qkv + 2 * DD + t + jbase * QKVD;
    const float* Pvp = Pv + t + jbase * DD;
    u64 T0[4] = {}, T1[4] = {};
#pragma unroll 2
    for (int jj = 0; jj < 256; jj++) {
        float pv = Pvp[jj * DD];
        float v = Vp[jj * QKVD];
        float s0 = silu_h(pvq0 - pv);
        float s1 = silu_h(pvq1 - pv);
        u64 s0p = pk2(s0, s0), s1p = pk2(s1, s1);
        ulonglong2 wA0 = *(const ulonglong2*)(gw0 + jj * HH);
        ulonglong2 wA1 = *(const ulonglong2*)(gw0 + jj * HH + 4);
        ulonglong2 wB0 = *(const ulonglong2*)(gw1 + jj * HH);
        ulonglong2 wB1 = *(const ulonglong2*)(gw1 + jj * HH + 4);
        T0[0] = fma2(s0p, wA0.x, T0[0]); T0[1] = fma2(s0p, wA0.y, T0[1]);
        T0[2] = fma2(s0p, wA1.x, T0[2]); T0[3] = fma2(s0p, wA1.y, T0[3]);
        T1[0] = fma2(s1p, wB0.x, T1[0]); T1[1] = fma2(s1p, wB0.y, T1[1]);
        T1[2] = fma2(s1p, wB1.x, T1[2]); T1[3] = fma2(s1p, wB1.y, T1[3]);
        c1a = fmaf(gw0[jj * HH + h], v, c1a);
        c1b = fmaf(gw1[jj * HH + h], v, c1b);
    }
    int b = pair * 2 + jh;
    float* T0g = Tp + (b * 2 + 0) * (HH * DD);
    float* T1g = Tp + (b * 2 + 1) * (HH * DD);
#pragma unroll
    for (int c = 0; c < 4; c++) {
        float2 a = up2(T0[c]);
        T0g[(2 * c) * DD + t] = a.x;
        T0g[(2 * c + 1) * DD + t] = a.y;
        float2 bb = up2(T1[c]);
        T1g[(2 * c) * DD + t] = bb.x;
        T1g[(2 * c + 1) * DD + t] = bb.y;
    }
    c1p[(b * 2 + 0) * DD + t] = c1a;
    c1p[(b * 2 + 1) * DD + t] = c1b;
}

// ---------------- attention 2b: combine + context2 + residual + fused LN2 -----------
__global__ __launch_bounds__(256, 3) void attn_fin(
    const float* __restrict__ x, const float* __restrict__ rv2T,
    const float* __restrict__ rv2_b, const float* __restrict__ Tp,
    const float* __restrict__ c1p,
    const float* __restrict__ ln2_w, const float* __restrict__ ln2_b,
    float* __restrict__ y, float* __restrict__ xn2) {
    const int pair = blockIdx.x;
    const int i0 = pair * 2;
    const int t = threadIdx.x;

    __shared__ __align__(16) float sm_T[2][HH * DD];   // combined T, 16KB
    __shared__ float sred[4][8];

    {
        const float4* A0 = (const float4*)(Tp + ((pair * 2 + 0) * 2 + 0) * (HH * DD));
        const float4* A1 = (const float4*)(Tp + ((pair * 2 + 1) * 2 + 0) * (HH * DD));
        const float4* B0 = (const float4*)(Tp + ((pair * 2 + 0) * 2 + 1) * (HH * DD));
        const float4* B1 = (const float4*)(Tp + ((pair * 2 + 1) * 2 + 1) * (HH * DD));
        float4* D0 = (float4*)sm_T[0];
        float4* D1 = (float4*)sm_T[1];
#pragma unroll
        for (int l = 0; l < 2; l++) {
            int idx = l * 256 + t;
            float4 a0 = A0[idx], a1 = A1[idx];
            float4 b0 = B0[idx], b1 = B1[idx];
            D0[idx] = make_float4(a0.x + a1.x, a0.y + a1.y, a0.z + a1.z, a0.w + a1.w);
            D1[idx] = make_float4(b0.x + b1.x, b0.y + b1.y, b0.z + b1.z, b0.w + b1.w);
        }
    }
    __syncthreads();

    const int d = t;
    const int h = d >> 5;
    float c1a = c1p[((pair * 2 + 0) * 2 + 0) * DD + d] + c1p[((pair * 2 + 1) * 2 + 0) * DD + d];
    float c1b = c1p[((pair * 2 + 0) * 2 + 1) * DD + d] + c1p[((pair * 2 + 1) * 2 + 1) * DD + d];

    float bv = rv2_b[d];
    float c2a = bv, c2b = bv;
    const float* T0s = sm_T[0] + h * DD;
    const float* T1s = sm_T[1] + h * DD;
#pragma unroll 8
    for (int k = 0; k < DD; k++) {
        float rv = rv2T[k * DD + d];
        c2a += rv * T0s[k];
        c2b += rv * T1s[k];
    }
    float y0 = x[i0 * DD + d] + c1a + c2a;
    float y1 = x[(i0 + 1) * DD + d] + c1b + c2b;
    y[i0 * DD + d] = y0;
    y[(i0 + 1) * DD + d] = y1;

    float s0 = y0, q0 = y0 * y0, s1 = y1, q1 = y1 * y1;
#pragma unroll
    for (int o = 16; o; o >>= 1) {
        s0 += __shfl_xor_sync(0xffffffff, s0, o);
        q0 += __shfl_xor_sync(0xffffffff, q0, o);
        s1 += __shfl_xor_sync(0xffffffff, s1, o);
        q1 += __shfl_xor_sync(0xffffffff, q1, o);
    }
    int warp = t >> 5, lane = t & 31;
    if (lane == 0) {
        sred[0][warp] = s0; sred[1][warp] = q0;
        sred[2][warp] = s1; sred[3][warp] = q1;
    }
    __syncthreads();
    float S0 = 0.f, Q0 = 0.f, S1 = 0.f, Q1 = 0.f;
#pragma unroll
    for (int k = 0; k < 8; k++) {
        S0 += sred[0][k]; Q0 += sred[1][k];
        S1 += sred[2][k]; Q1 += sred[3][k];
    }
    float m0 = S0 * (1.0f / DD), m1 = S1 * (1.0f / DD);
    float v0 = Q0 * (1.0f / DD) - m0 * m0;
    float v1 = Q1 * (1.0f / DD) - m1 * m1;
    float lw = ln2_w[d], lb = ln2_b[d];
    xn2[i0 * DD + d] = (y0 - m0) * rsqrtf(v0 + 1e-5f) * lw + lb;
    xn2[(i0 + 1) * DD + d] = (y1 - m1) * rsqrtf(v1 + 1e-5f) * lw + lb;
}

// ---------------- host launcher ----------------
extern "C" void kernel_launch(void* const* d_in, const int* in_sizes, int n_in,
                              void* d_out, int out_size) {
    const float* x      = (const float*)d_in[0];
    const float* coords = (const float*)d_in[1];
    const float* ln1_w  = (const float*)d_in[2];
    const float* ln1_b  = (const float*)d_in[3];
    const float* ln2_w  = (const float*)d_in[4];
    const float* ln2_b  = (const float*)d_in[5];
    const float* qkv_w  = (const float*)d_in[6];
    const float* qkv_b  = (const float*)d_in[7];
    const float* rb1_w  = (const float*)d_in[8];
    const float* rb1_b  = (const float*)d_in[9];
    const float* rb2_w  = (const float*)d_in[10];
    const float* rb2_b  = (const float*)d_in[11];
    const float* rv1_w  = (const float*)d_in[12];
    const float* rv1_b  = (const float*)d_in[13];
    const float* rv2_w  = (const float*)d_in[14];
    const float* rv2_b  = (const float*)d_in[15];
    const float* ffn_w1 = (const float*)d_in[16];
    const float* ffn_b1 = (const float*)d_in[17];
    const float* ffn_w2 = (const float*)d_in[18];
    const float* ffn_b2 = (const float*)d_in[19];
    const float* ffn_w3 = (const float*)d_in[20];
    const float* ffn_b3 = (const float*)d_in[21];
    float* out = (float*)d_out;

    float *p_xn, *p_qkv, *p_Pb, *p_Pv, *p_rv2T, *p_w, *p_Tp, *p_c1p, *p_y, *p_xn2, *p_h1;
    float2* p_PKT;
    cudaGetSymbolAddress((void**)&p_xn, g_xn);
    cudaGetSymbolAddress((void**)&p_qkv, g_qkv);
    cudaGetSymbolAddress((void**)&p_PKT, g_PKT);
    cudaGetSymbolAddress((void**)&p_Pb, g_Pb);
    cudaGetSymbolAddress((void**)&p_Pv, g_Pv);
    cudaGetSymbolAddress((void**)&p_rv2T, g_rv2T);
    cudaGetSymbolAddress((void**)&p_w, g_w);
    cudaGetSymbolAddress((void**)&p_Tp, g_Tp);
    cudaGetSymbolAddress((void**)&p_c1p, g_c1p);
    cudaGetSymbolAddress((void**)&p_y, g_y);
    cudaGetSymbolAddress((void**)&p_xn2, g_xn2);
    cudaGetSymbolAddress((void**)&p_h1, g_h1);

    dim3 tthr(32, 8);

    // 1. LN1
    ln_kernel<<<NB, 256>>>(x, ln1_w, ln1_b, p_xn);
    // 2. QKV = xn @ qkv_w^T + qkv_b  (+ K^T side-write into PKT.x)
    gemm_t<<<dim3(QKVD / 64, NB / 32), 256>>>(p_xn, qkv_w, qkv_b, p_PKT, p_qkv,
                                              NB, QKVD, DD);
    // 3. coords projections (half-scaled: Pb, PKT.y, Pv)
    proj3_kernel<<<NB, 256>>>(coords, rb1_w, rv1_w, p_Pb, p_PKT, p_Pv);
    // 4. attention 1a: raw logits (j-pair threads, 512 blocks x 128 thr)
    attn_logits<<<dim3(NB / 2, 2), 128>>>(p_qkv, p_PKT, p_Pb, rb1_b, rb2_w, rb2_b, p_w);
    // 5. rv2^T
    transpose_kernel<<<dim3(DD / 32, DD / 32), tthr>>>(rv2_w, p_rv2T, DD, DD, DD, 0);
    // 6. attention 1b: softmax in place
    softmax_kernel<<<NB, 256>>>(p_w);
    // 7. attention 2a: partial T + c1 (j-split, 512 blocks)
    attn_ctx<<<dim3(NB / 2, 2), 256>>>(p_qkv, p_Pv, rv1_b, p_w, p_Tp, p_c1p);
    // 8. attention 2b: combine + c2 + residual + fused LN2
    attn_fin<<<NB / 2, 256>>>(x, p_rv2T, rv2_b, p_Tp, p_c1p, ln2_w, ln2_b, p_y, p_xn2);
    // 9. fused SwiGLU dual-GEMM
    gemm_swiglu<<<dim3((HID + 63) / 64, NB / 32), 256>>>(p_xn2, ffn_w1, ffn_b1,
                                                         ffn_w2, ffn_b2, p_h1,
                                                         NB, HID, DD);
    // 10. out = h1 @ ffn_w3^T + ffn_b3 + y   (32x32 tiles -> 128 blocks)
    gemm_t32<<<dim3(DD / 32, NB / 32), 256>>>(p_h1, ffn_w3, ffn_b3, p_y, out,
                                              NB, DD, HID);
}

// round 12
// speedup vs baseline: 1.0162x; 1.0162x over previous
#include <cuda_runtime.h>
#include <cuda_bf16.h>

// Shapes (compile-time constants)
#define NB   512           // sequence length
#define DD   256           // model dim
#define HH   8             // heads
#define HID  682           // swiglu hidden
#define QKVD 768

typedef unsigned long long u64;

// ---------------- device scratch ----------------
__device__ float g_xn[NB * DD];
__device__ float g_qkv[NB * QKVD];
__device__ float2 g_PKT[DD * NB];    // (.x = K^T[k][j], .y = 0.5*Pb^T[k][j])
__device__ float g_Pb[NB * DD];      // 0.5 * Pb
__device__ float g_Pv[NB * DD];      // 0.5 * Pv
__device__ float g_rv2T[DD * DD];    // rv2 transposed [k][d]
__device__ float g_w[NB * NB * HH];  // logit partial kh=0 -> final softmax weights (8MB)
__device__ float g_w2[NB * NB * HH]; // logit partial kh=1 (8MB)
__device__ float g_Tp[NB * 2 * HH * DD];   // partial T (8MB)
__device__ float g_c1p[NB * 2 * DD];       // partial c1 (1MB)
__device__ float g_y[NB * DD];
__device__ float g_xn2[NB * DD];
__device__ float g_h1[NB * HID];

// ---- packed f32x2 helpers (sm_100+) ----
__device__ __forceinline__ u64 pk2(float lo, float hi) {
    u64 r;
    asm("mov.b64 %0, {%1, %2};" : "=l"(r) : "f"(lo), "f"(hi));
    return r;
}
__device__ __forceinline__ float2 up2(u64 v) {
    float2 f;
    asm("mov.b64 {%0, %1}, %2;" : "=f"(f.x), "=f"(f.y) : "l"(v));
    return f;
}
__device__ __forceinline__ u64 fma2(u64 a, u64 b, u64 c) {
    u64 d;
    asm("fma.rn.f32x2 %0, %1, %2, %3;" : "=l"(d) : "l"(a), "l"(b), "l"(c));
    return d;
}
__device__ __forceinline__ u64 add2(u64 a, u64 b) {
    u64 d;
    asm("add.rn.f32x2 %0, %1, %2;" : "=l"(d) : "l"(a), "l"(b));
    return d;
}

// silu from the HALF-difference s = 0.5*(a-b): silu(a-b) = s*tanh(s)+s
__device__ __forceinline__ float silu_h(float s) {
    float t;
    asm("tanh.approx.f32 %0, %1;" : "=f"(t) : "f"(s));
    return fmaf(s, t, s);
}
// accurate silu for the (cold) FFN epilogue
__device__ __forceinline__ float silu_acc(float v) {
    return v / (1.0f + __expf(-v));
}

// ---------------- LayerNorm: one block per row, 256 threads ----------------
__global__ __launch_bounds__(256) void ln_kernel(const float* __restrict__ x,
                                                 const float* __restrict__ w,
                                                 const float* __restrict__ b,
                                                 float* __restrict__ out) {
    int row = blockIdx.x, t = threadIdx.x;
    float v = x[row * DD + t];
    float s = v, q = v * v;
#pragma unroll
    for (int o = 16; o; o >>= 1) {
        s += __shfl_xor_sync(0xffffffff, s, o);
        q += __shfl_xor_sync(0xffffffff, q, o);
    }
    __shared__ float ss[8], sq[8];
    int warp = t >> 5, lane = t & 31;
    if (lane == 0) { ss[warp] = s; sq[warp] = q; }
    __syncthreads();
    s = 0.f; q = 0.f;
#pragma unroll
    for (int k = 0; k < 8; k++) { s += ss[k]; q += sq[k]; }
    float mean = s * (1.0f / DD);
    float var = q * (1.0f / DD) - mean * mean;
    out[row * DD + t] = (v - mean) * rsqrtf(var + 1e-5f) * w[t] + b[t];
}

// ---------------- coords projection (all outputs HALF-scaled) ----------------
__global__ __launch_bounds__(256) void proj3_kernel(const float* __restrict__ coords,
                                                    const float* __restrict__ rb1,
                                                    const float* __restrict__ rv1,
                                                    float* __restrict__ Pb,
                                                    float2* __restrict__ PKT,
                                                    float* __restrict__ Pv) {
    int i = blockIdx.x, k = threadIdx.x;
    float c0 = coords[i * 3 + 0], c1 = coords[i * 3 + 1], c2 = coords[i * 3 + 2];
    float pb = rb1[k * 3 + 0] * c0 + rb1[k * 3 + 1] * c1 + rb1[k * 3 + 2] * c2;
    float pv = rv1[k * 3 + 0] * c0 + rv1[k * 3 + 1] * c1 + rv1[k * 3 + 2] * c2;
    Pb[i * DD + k] = 0.5f * pb;
    PKT[k * NB + i].y = 0.5f * pb;
    Pv[i * DD + k] = 0.5f * pv;
}

// ---------------- generic 32x32-tiled transpose ----------------
__global__ __launch_bounds__(256) void transpose_kernel(const float* __restrict__ in,
                                                        float* __restrict__ out,
                                                        int R, int C, int ldin, int off) {
    __shared__ float tile[32][33];
    int c0 = blockIdx.x * 32, r0 = blockIdx.y * 32;
    int tx = threadIdx.x, ty = threadIdx.y;  // 32 x 8
#pragma unroll
    for (int s = 0; s < 32; s += 8)
        tile[ty + s][tx] = in[(r0 + ty + s) * ldin + off + c0 + tx];
    __syncthreads();
#pragma unroll
    for (int s = 0; s < 32; s += 8)
        out[(c0 + ty + s) * R + r0 + tx] = tile[tx][ty + s];
}

// ---------------- GEMM: C = A @ W^T (+bias), 32x64 tile; optional K^T side-write ----
__global__ __launch_bounds__(256, 2) void gemm_t(const float* __restrict__ A,
                                                 const float* __restrict__ W,
                                                 const float* __restrict__ bias,
                                                 float2* __restrict__ PKT,  // nullable
                                                 float* __restrict__ C,
                                                 int M, int N, int K) {
    __shared__ __align__(16) u64 As[32][34];     // [k][m] duplicated
    __shared__ __align__(16) float Ws[32][68];   // [k][n]
    int tid = threadIdx.x;
    int tx = tid & 15, ty = tid >> 4;            // tx -> n (4 cols), ty -> m (2 rows)
    int row0 = blockIdx.y * 32, col0 = blockIdx.x * 64;
    u64 acc[2][2] = {};
    for (int k0 = 0; k0 < K; k0 += 32) {
#pragma unroll
        for (int l = 0; l < 4; l++) {            // A: 32x32
            int idx = l * 256 + tid;
            int m = idx >> 5, k = idx & 31;
            int gk = k0 + k, ar = row0 + m;
            float v = (ar < M && gk < K) ? A[ar * K + gk] : 0.f;
            As[k][m] = pk2(v, v);
        }
#pragma unroll
        for (int l = 0; l < 8; l++) {            // W: 64x32
            int idx = l * 256 + tid;
            int m = idx >> 5, k = idx & 31;
            int gk = k0 + k, wr = col0 + m;
            Ws[k][m] = (wr < N && gk < K) ? W[wr * K + gk] : 0.f;
        }
        __syncthreads();
#pragma unroll
        for (int kk = 0; kk < 32; kk++) {
            ulonglong2 Av = *(const ulonglong2*)&As[kk][ty * 2];
            ulonglong2 Bv = *(const ulonglong2*)&Ws[kk][tx * 4];
            acc[0][0] = fma2(Av.x, Bv.x, acc[0][0]);
            acc[0][1] = fma2(Av.x, Bv.y, acc[0][1]);
            acc[1][0] = fma2(Av.y, Bv.x, acc[1][0]);
            acc[1][1] = fma2(Av.y, Bv.y, acc[1][1]);
        }
        __syncthreads();
    }
#pragma unroll
    for (int r = 0; r < 2; r++) {
        int m = row0 + ty * 2 + r;
        if (m >= M) continue;
#pragma unroll
        for (int c2 = 0; c2 < 2; c2++) {
            float2 v = up2(acc[r][c2]);
            int n0 = col0 + tx * 4 + c2 * 2;
            if (n0 < N) {
                float o = v.x + (bias ? bias[n0] : 0.f);
                C[m * N + n0] = o;
                if (PKT && n0 >= DD && n0 < 2 * DD) PKT[(n0 - DD) * NB + m].x = o;
            }
            if (n0 + 1 < N) {
                float o = v.y + (bias ? bias[n0 + 1] : 0.f);
                C[m * N + n0 + 1] = o;
                if (PKT && n0 + 1 >= DD && n0 + 1 < 2 * DD) PKT[(n0 + 1 - DD) * NB + m].x = o;
            }
        }
    }
}

// ---------------- GEMM 32x32 tile (better grid fill for small N) ----------------
__global__ __launch_bounds__(256, 3) void gemm_t32(const float* __restrict__ A,
                                                   const float* __restrict__ W,
                                                   const float* __restrict__ bias,
                                                   const float* __restrict__ residual,
                                                   float* __restrict__ C,
                                                   int M, int N, int K) {
    __shared__ __align__(16) u64 As[32][34];     // [k][m] duplicated
    __shared__ __align__(16) float Ws[32][36];   // [k][n]
    int tid = threadIdx.x;
    int tx = tid & 7, ty = tid >> 3;             // tx -> n (4 cols), ty -> m (1 row)
    int row0 = blockIdx.y * 32, col0 = blockIdx.x * 32;
    u64 acc[2] = {};
    for (int k0 = 0; k0 < K; k0 += 32) {
#pragma unroll
        for (int l = 0; l < 4; l++) {
            int idx = l * 256 + tid;
            int m = idx >> 5, k = idx & 31;
            int gk = k0 + k;
            int ar = row0 + m, wr = col0 + m;
            float va = (ar < M && gk < K) ? A[ar * K + gk] : 0.f;
            As[k][m] = pk2(va, va);
            Ws[k][m] = (wr < N && gk < K) ? W[wr * K + gk] : 0.f;
        }
        __syncthreads();
#pragma unroll
        for (int kk = 0; kk < 32; kk++) {
            u64 Av = As[kk][ty];
            ulonglong2 Bv = *(const ulonglong2*)&Ws[kk][tx * 4];
            acc[0] = fma2(Av, Bv.x, acc[0]);
            acc[1] = fma2(Av, Bv.y, acc[1]);
        }
        __syncthreads();
    }
    int m = row0 + ty;
    if (m < M) {
#pragma unroll
        for (int c2 = 0; c2 < 2; c2++) {
            float2 v = up2(acc[c2]);
            int n0 = col0 + tx * 4 + c2 * 2;
            if (n0 < N) {
                float o = v.x;
                if (bias) o += bias[n0];
                if (residual) o += residual[m * N + n0];
                C[m * N + n0] = o;
            }
            if (n0 + 1 < N) {
                float o = v.y;
                if (bias) o += bias[n0 + 1];
                if (residual) o += residual[m * N + n0 + 1];
                C[m * N + n0 + 1] = o;
            }
        }
    }
}

// ---------------- fused SwiGLU dual-GEMM, 32x64 tile ----------------
__global__ __launch_bounds__(256, 2) void gemm_swiglu(const float* __restrict__ A,
                                                      const float* __restrict__ W1,
                                                      const float* __restrict__ b1,
                                                      const float* __restrict__ W2,
                                                      const float* __restrict__ b2,
                                                      float* __restrict__ Hout,
                                                      int M, int N, int K) {
    __shared__ __align__(16) u64 As[32][34];
    __shared__ __align__(16) float W1s[32][68];
    __shared__ __align__(16) float W2s[32][68];
    int tid = threadIdx.x;
    int tx = tid & 15, ty = tid >> 4;
    int row0 = blockIdx.y * 32, col0 = blockIdx.x * 64;
    u64 acc1[2][2] = {};
    u64 acc2[2][2] = {};
    for (int k0 = 0; k0 < K; k0 += 32) {
#pragma unroll
        for (int l = 0; l < 4; l++) {
            int idx = l * 256 + tid;
            int m = idx >> 5, k = idx & 31;
            int gk = k0 + k, ar = row0 + m;
            float v = (ar < M && gk < K) ? A[ar * K + gk] : 0.f;
            As[k][m] = pk2(v, v);
        }
#pragma unroll
        for (int l = 0; l < 8; l++) {
            int idx = l * 256 + tid;
            int m = idx >> 5, k = idx & 31;
            int gk = k0 + k, wr = col0 + m;
            W1s[k][m] = (wr < N && gk < K) ? W1[wr * K + gk] : 0.f;
            W2s[k][m] = (wr < N && gk < K) ? W2[wr * K + gk] : 0.f;
        }
        __syncthreads();
#pragma unroll
        for (int kk = 0; kk < 32; kk++) {
            ulonglong2 Av = *(const ulonglong2*)&As[kk][ty * 2];
            ulonglong2 Bv = *(const ulonglong2*)&W1s[kk][tx * 4];
            ulonglong2 Cv = *(const ulonglong2*)&W2s[kk][tx * 4];
            acc1[0][0] = fma2(Av.x, Bv.x, acc1[0][0]);
            acc1[0][1] = fma2(Av.x, Bv.y, acc1[0][1]);
            acc1[1][0] = fma2(Av.y, Bv.x, acc1[1][0]);
            acc1[1][1] = fma2(Av.y, Bv.y, acc1[1][1]);
            acc2[0][0] = fma2(Av.x, Cv.x, acc2[0][0]);
            acc2[0][1] = fma2(Av.x, Cv.y, acc2[0][1]);
            acc2[1][0] = fma2(Av.y, Cv.x, acc2[1][0]);
            acc2[1][1] = fma2(Av.y, Cv.y, acc2[1][1]);
        }
        __syncthreads();
    }
#pragma unroll
    for (int r = 0; r < 2; r++) {
        int m = row0 + ty * 2 + r;
        if (m >= M) continue;
#pragma unroll
        for (int c2 = 0; c2 < 2; c2++) {
            float2 v1 = up2(acc1[r][c2]);
            float2 v2 = up2(acc2[r][c2]);
            int n0 = col0 + tx * 4 + c2 * 2;
            if (n0 < N)
                Hout[m * N + n0] = silu_acc(v1.x + b1[n0]) * (v2.x + b2[n0]);
            if (n0 + 1 < N)
                Hout[m * N + n0 + 1] = silu_acc(v1.y + b1[n0 + 1]) * (v2.y + b2[n0 + 1]);
        }
    }
}

// ---------------- attention 1a: partial logits, split over (j-half, k-half) --------
// grid (NB/2 pairs, 2 j-halves, 2 k-halves), 256 threads; thread owns one j, 2 queries.
// Each block accumulates bias over its k-half for ALL 8 heads; qk for head h lives
// entirely in k-half h>>2 (heads 0-3 in kh=0, 4-7 in kh=1). Partials summed in softmax.
__global__ __launch_bounds__(256, 4) void attn_logits(
    const float* __restrict__ qkv, const float2* __restrict__ PKT,
    const float* __restrict__ Pb, const float* __restrict__ rb1_b,
    const float* __restrict__ rb2_w, const float* __restrict__ rb2_b,
    float* __restrict__ gw_p0, float* __restrict__ gw_p1) {
    const int i0 = blockIdx.x * 2;
    const int j = blockIdx.y * 256 + threadIdx.x;
    const int kh = blockIdx.z;
    const int kbase = kh * 128;
    const int t = threadIdx.x;

    __shared__ __align__(16) float4 sm_qpq[128];       // (q0, hpb0, q1, hpb1) for k-half
    __shared__ __align__(16) float sm_rb2[128 * HH];   // rb2 transposed [k'][h], k-half

    if (t < 128) {
        int k = kbase + t;
        float hb = 0.5f * rb1_b[k];
        sm_qpq[t] = make_float4(qkv[i0 * QKVD + k], Pb[i0 * DD + k] + hb,
                                qkv[(i0 + 1) * QKVD + k], Pb[(i0 + 1) * DD + k] + hb);
    }
#pragma unroll
    for (int l = 0; l < 4; l++) {
        int idx = l * 256 + t;          // 0..1023
        int h = idx >> 7, kp = idx & 127;
        sm_rb2[kp * HH + h] = rb2_w[h * DD + kbase + kp];
    }
    __syncthreads();

    u64 bias[2][4] = {};   // [q][head pair], partial over this k-half
    const float sc = 0.17677669529663687f;
#pragma unroll
    for (int hq = 0; hq < 4; hq++) {     // local head block: global head = kh*4+hq
        float qk0 = 0.f, qk1 = 0.f;
#pragma unroll 4
        for (int kk = 0; kk < 32; kk++) {
            int kp = hq * 32 + kk;
            float2 pk = PKT[(kbase + kp) * NB + j];
            ulonglong2 rA = *(const ulonglong2*)(sm_rb2 + kp * HH);
            ulonglong2 rB = *(const ulonglong2*)(sm_rb2 + kp * HH + 4);
            float4 qq = sm_qpq[kp];
            qk0 = fmaf(qq.x, pk.x, qk0);
            qk1 = fmaf(qq.z, pk.x, qk1);
            float u0 = silu_h(qq.y - pk.y);
            float u1 = silu_h(qq.w - pk.y);
            u64 u0p = pk2(u0, u0);
            u64 u1p = pk2(u1, u1);
            bias[0][0] = fma2(u0p, rA.x, bias[0][0]);
            bias[0][1] = fma2(u0p, rA.y, bias[0][1]);
            bias[0][2] = fma2(u0p, rB.x, bias[0][2]);
            bias[0][3] = fma2(u0p, rB.y, bias[0][3]);
            bias[1][0] = fma2(u1p, rA.x, bias[1][0]);
            bias[1][1] = fma2(u1p, rA.y, bias[1][1]);
            bias[1][2] = fma2(u1p, rB.x, bias[1][2]);
            bias[1][3] = fma2(u1p, rB.y, bias[1][3]);
        }
        // fold qk*sc into GLOBAL head h = kh*4+hq -> pair c = h>>1, lane h&1
        int hg = kh * 4 + hq;
        int c = hg >> 1;
        u64 p0 = (hg & 1) ? pk2(0.f, qk0 * sc) : pk2(qk0 * sc, 0.f);
        u64 p1 = (hg & 1) ? pk2(0.f, qk1 * sc) : pk2(qk1 * sc, 0.f);
        bias[0][c] = add2(bias[0][c], p0);
        bias[1][c] = add2(bias[1][c], p1);
    }
    // write partial logits (rb2_b folded into kh=0 partial only)
    float* gw_part = kh ? gw_p1 : gw_p0;
    u64* w0 = (u64*)(gw_part + i0 * NB * HH + j * HH);
    u64* w1 = (u64*)(gw_part + (i0 + 1) * NB * HH + j * HH);
    if (kh == 0) {
#pragma unroll
        for (int c = 0; c < 4; c++) {
            u64 bb = pk2(rb2_b[2 * c], rb2_b[2 * c + 1]);
            w0[c] = add2(bias[0][c], bb);
            w1[c] = add2(bias[1][c], bb);
        }
    } else {
#pragma unroll
        for (int c = 0; c < 4; c++) {
            w0[c] = bias[0][c];
            w1[c] = bias[1][c];
        }
    }
}

// ---------------- attention 1b: combine partials + softmax -> gw_p0 -----------------
__global__ __launch_bounds__(256, 4) void softmax_kernel(float* __restrict__ gw_all,
                                                         const float* __restrict__ gw_b) {
    const int i = blockIdx.x;
    const int t = threadIdx.x;
    __shared__ float sw[NB * 9];   // padded [j][9] for conflict-free per-head access

    float4* gw4 = (float4*)(gw_all + i * NB * HH);
    const float4* gwb4 = (const float4*)(gw_b + i * NB * HH);
#pragma unroll
    for (int l = 0; l < 4; l++) {
        int idx = l * 256 + t;              // 1024 float4
        float4 v = gw4[idx];
        float4 vb = gwb4[idx];
        v.x += vb.x; v.y += vb.y; v.z += vb.z; v.w += vb.w;
        int jj = idx >> 1, half = (idx & 1) * 4;
        sw[jj * 9 + half + 0] = v.x;
        sw[jj * 9 + half + 1] = v.y;
        sw[jj * 9 + half + 2] = v.z;
        sw[jj * 9 + half + 3] = v.w;
    }
    __syncthreads();
    {
        int h = t >> 5, lane = t & 31;
        float m = -1e30f;
        for (int jj = lane; jj < NB; jj += 32) m = fmaxf(m, sw[jj * 9 + h]);
#pragma unroll
        for (int o = 16; o; o >>= 1) m = fmaxf(m, __shfl_xor_sync(0xffffffff, m, o));
        float s = 0.f;
        for (int jj = lane; jj < NB; jj += 32) {
            float e = __expf(sw[jj * 9 + h] - m);
            sw[jj * 9 + h] = e;
            s += e;
        }
#pragma unroll
        for (int o = 16; o; o >>= 1) s += __shfl_xor_sync(0xffffffff, s, o);
        float inv = 1.0f / s;
        for (int jj = lane; jj < NB; jj += 32) sw[jj * 9 + h] *= inv;
    }
    __syncthreads();
#pragma unroll
    for (int l = 0; l < 4; l++) {
        int idx = l * 256 + t;
        int jj = idx >> 1, half = (idx & 1) * 4;
        float4 v;
        v.x = sw[jj * 9 + half + 0];
        v.y = sw[jj * 9 + half + 1];
        v.z = sw[jj * 9 + half + 2];
        v.w = sw[jj * 9 + half + 3];
        gw4[idx] = v;
    }
}

// ---------------- attention 2a: partial T + partial c1, split over j halves ---------
__global__ __launch_bounds__(256, 4) void attn_ctx(
    const float* __restrict__ qkv, const float* __restrict__ Pv,
    const float* __restrict__ rv1_b, const float* __restrict__ gw_all,
    float* __restrict__ Tp, float* __restrict__ c1p) {
    const int pair = blockIdx.x;
    const int jh = blockIdx.y;
    const int i0 = pair * 2;
    const int jbase = jh * 256;
    const int t = threadIdx.x;

    __shared__ __align__(16) float sm_gw[2][256 * HH];  // staged weights (j half), 16KB

    {
        const float4* s0 = (const float4*)(gw_all + i0 * NB * HH + jbase * HH);
        const float4* s1 = (const float4*)(gw_all + (i0 + 1) * NB * HH + jbase * HH);
        float4* d0 = (float4*)sm_gw[0];
        float4* d1 = (float4*)sm_gw[1];
#pragma unroll
        for (int l = 0; l < 2; l++) {
            int idx = l * 256 + t;
            d0[idx] = s0[idx];
            d1[idx] = s1[idx];
        }
    }
    __syncthreads();

    const float* gw0 = sm_gw[0];
    const float* gw1 = sm_gw[1];
    const int h = t >> 5;
    float c1a = 0.f, c1b = 0.f;

    float pvb = 0.5f * rv1_b[t];
    float pvq0 = Pv[i0 * DD + t] + pvb;
    float pvq1 = Pv[(i0 + 1) * DD + t] + pvb;
    const float* Vp = qkv + 2 * DD + t + jbase * QKVD;
    const float* Pvp = Pv + t + jbase * DD;
    u64 T0[4] = {}, T1[4] = {};
#pragma unroll 2
    for (int jj = 0; jj < 256; jj++) {
        float pv = Pvp[jj * DD];
        float v = Vp[jj * QKVD];
        float s0 = silu_h(pvq0 - pv);
        float s1 = silu_h(pvq1 - pv);
        u64 s0p = pk2(s0, s0), s1p = pk2(s1, s1);
        ulonglong2 wA0 = *(const ulonglong2*)(gw0 + jj * HH);
        ulonglong2 wA1 = *(const ulonglong2*)(gw0 + jj * HH + 4);
        ulonglong2 wB0 = *(const ulonglong2*)(gw1 + jj * HH);
        ulonglong2 wB1 = *(const ulonglong2*)(gw1 + jj * HH + 4);
        T0[0] = fma2(s0p, wA0.x, T0[0]); T0[1] = fma2(s0p, wA0.y, T0[1]);
        T0[2] = fma2(s0p, wA1.x, T0[2]); T0[3] = fma2(s0p, wA1.y, T0[3]);
        T1[0] = fma2(s1p, wB0.x, T1[0]); T1[1] = fma2(s1p, wB0.y, T1[1]);
        T1[2] = fma2(s1p, wB1.x, T1[2]); T1[3] = fma2(s1p, wB1.y, T1[3]);
        c1a = fmaf(gw0[jj * HH + h], v, c1a);
        c1b = fmaf(gw1[jj * HH + h], v, c1b);
    }
    int b = pair * 2 + jh;
    float* T0g = Tp + (b * 2 + 0) * (HH * DD);
    float* T1g = Tp + (b * 2 + 1) * (HH * DD);
#pragma unroll
    for (int c = 0; c < 4; c++) {
        float2 a = up2(T0[c]);
        T0g[(2 * c) * DD + t] = a.x;
        T0g[(2 * c + 1) * DD + t] = a.y;
        float2 bb = up2(T1[c]);
        T1g[(2 * c) * DD + t] = bb.x;
        T1g[(2 * c + 1) * DD + t] = bb.y;
    }
    c1p[(b * 2 + 0) * DD + t] = c1a;
    c1p[(b * 2 + 1) * DD + t] = c1b;
}

// ---------------- attention 2b: combine + context2 + residual + fused LN2 -----------
__global__ __launch_bounds__(256, 3) void attn_fin(
    const float* __restrict__ x, const float* __restrict__ rv2T,
    const float* __restrict__ rv2_b, const float* __restrict__ Tp,
    const float* __restrict__ c1p,
    const float* __restrict__ ln2_w, const float* __restrict__ ln2_b,
    float* __restrict__ y, float* __restrict__ xn2) {
    const int pair = blockIdx.x;
    const int i0 = pair * 2;
    const int t = threadIdx.x;

    __shared__ __align__(16) float sm_T[2][HH * DD];   // combined T, 16KB
    __shared__ float sred[4][8];

    {
        const float4* A0 = (const float4*)(Tp + ((pair * 2 + 0) * 2 + 0) * (HH * DD));
        const float4* A1 = (const float4*)(Tp + ((pair * 2 + 1) * 2 + 0) * (HH * DD));
        const float4* B0 = (const float4*)(Tp + ((pair * 2 + 0) * 2 + 1) * (HH * DD));
        const float4* B1 = (const float4*)(Tp + ((pair * 2 + 1) * 2 + 1) * (HH * DD));
        float4* D0 = (float4*)sm_T[0];
        float4* D1 = (float4*)sm_T[1];
#pragma unroll
        for (int l = 0; l < 2; l++) {
            int idx = l * 256 + t;
            float4 a0 = A0[idx], a1 = A1[idx];
            float4 b0 = B0[idx], b1 = B1[idx];
            D0[idx] = make_float4(a0.x + a1.x, a0.y + a1.y, a0.z + a1.z, a0.w + a1.w);
            D1[idx] = make_float4(b0.x + b1.x, b0.y + b1.y, b0.z + b1.z, b0.w + b1.w);
        }
    }
    __syncthreads();

    const int d = t;
    const int h = d >> 5;
    float c1a = c1p[((pair * 2 + 0) * 2 + 0) * DD + d] + c1p[((pair * 2 + 1) * 2 + 0) * DD + d];
    float c1b = c1p[((pair * 2 + 0) * 2 + 1) * DD + d] + c1p[((pair * 2 + 1) * 2 + 1) * DD + d];

    float bv = rv2_b[d];
    float c2a = bv, c2b = bv;
    const float* T0s = sm_T[0] + h * DD;
    const float* T1s = sm_T[1] + h * DD;
#pragma unroll 8
    for (int k = 0; k < DD; k++) {
        float rv = rv2T[k * DD + d];
        c2a += rv * T0s[k];
        c2b += rv * T1s[k];
    }
    float y0 = x[i0 * DD + d] + c1a + c2a;
    float y1 = x[(i0 + 1) * DD + d] + c1b + c2b;
    y[i0 * DD + d] = y0;
    y[(i0 + 1) * DD + d] = y1;

    float s0 = y0, q0 = y0 * y0, s1 = y1, q1 = y1 * y1;
#pragma unroll
    for (int o = 16; o; o >>= 1) {
        s0 += __shfl_xor_sync(0xffffffff, s0, o);
        q0 += __shfl_xor_sync(0xffffffff, q0, o);
        s1 += __shfl_xor_sync(0xffffffff, s1, o);
        q1 += __shfl_xor_sync(0xffffffff, q1, o);
    }
    int warp = t >> 5, lane = t & 31;
    if (lane == 0) {
        sred[0][warp] = s0; sred[1][warp] = q0;
        sred[2][warp] = s1; sred[3][warp] = q1;
    }
    __syncthreads();
    float S0 = 0.f, Q0 = 0.f, S1 = 0.f, Q1 = 0.f;
#pragma unroll
    for (int k = 0; k < 8; k++) {
        S0 += sred[0][k]; Q0 += sred[1][k];
        S1 += sred[2][k]; Q1 += sred[3][k];
    }
    float m0 = S0 * (1.0f / DD), m1 = S1 * (1.0f / DD);
    float v0 = Q0 * (1.0f / DD) - m0 * m0;
    float v1 = Q1 * (1.0f / DD) - m1 * m1;
    float lw = ln2_w[d], lb = ln2_b[d];
    xn2[i0 * DD + d] = (y0 - m0) * rsqrtf(v0 + 1e-5f) * lw + lb;
    xn2[(i0 + 1) * DD + d] = (y1 - m1) * rsqrtf(v1 + 1e-5f) * lw + lb;
}

// ---------------- host launcher ----------------
extern "C" void kernel_launch(void* const* d_in, const int* in_sizes, int n_in,
                              void* d_out, int out_size) {
    const float* x      = (const float*)d_in[0];
    const float* coords = (const float*)d_in[1];
    const float* ln1_w  = (const float*)d_in[2];
    const float* ln1_b  = (const float*)d_in[3];
    const float* ln2_w  = (const float*)d_in[4];
    const float* ln2_b  = (const float*)d_in[5];
    const float* qkv_w  = (const float*)d_in[6];
    const float* qkv_b  = (const float*)d_in[7];
    const float* rb1_w  = (const float*)d_in[8];
    const float* rb1_b  = (const float*)d_in[9];
    const float* rb2_w  = (const float*)d_in[10];
    const float* rb2_b  = (const float*)d_in[11];
    const float* rv1_w  = (const float*)d_in[12];
    const float* rv1_b  = (const float*)d_in[13];
    const float* rv2_w  = (const float*)d_in[14];
    const float* rv2_b  = (const float*)d_in[15];
    const float* ffn_w1 = (const float*)d_in[16];
    const float* ffn_b1 = (const float*)d_in[17];
    const float* ffn_w2 = (const float*)d_in[18];
    const float* ffn_b2 = (const float*)d_in[19];
    const float* ffn_w3 = (const float*)d_in[20];
    const float* ffn_b3 = (const float*)d_in[21];
    float* out = (float*)d_out;

    float *p_xn, *p_qkv, *p_Pb, *p_Pv, *p_rv2T, *p_w, *p_w2, *p_Tp, *p_c1p, *p_y, *p_xn2, *p_h1;
    float2* p_PKT;
    cudaGetSymbolAddress((void**)&p_xn, g_xn);
    cudaGetSymbolAddress((void**)&p_qkv, g_qkv);
    cudaGetSymbolAddress((void**)&p_PKT, g_PKT);
    cudaGetSymbolAddress((void**)&p_Pb, g_Pb);
    cudaGetSymbolAddress((void**)&p_Pv, g_Pv);
    cudaGetSymbolAddress((void**)&p_rv2T, g_rv2T);
    cudaGetSymbolAddress((void**)&p_w, g_w);
    cudaGetSymbolAddress((void**)&p_w2, g_w2);
    cudaGetSymbolAddress((void**)&p_Tp, g_Tp);
    cudaGetSymbolAddress((void**)&p_c1p, g_c1p);
    cudaGetSymbolAddress((void**)&p_y, g_y);
    cudaGetSymbolAddress((void**)&p_xn2, g_xn2);
    cudaGetSymbolAddress((void**)&p_h1, g_h1);

    dim3 tthr(32, 8);

    // 1. LN1
    ln_kernel<<<NB, 256>>>(x, ln1_w, ln1_b, p_xn);
    // 2. QKV = xn @ qkv_w^T + qkv_b  (+ K^T side-write into PKT.x)
    gemm_t<<<dim3(QKVD / 64, NB / 32), 256>>>(p_xn, qkv_w, qkv_b, p_PKT, p_qkv,
                                              NB, QKVD, DD);
    // 3. coords projections (half-scaled: Pb, PKT.y, Pv)
    proj3_kernel<<<NB, 256>>>(coords, rb1_w, rv1_w, p_Pb, p_PKT, p_Pv);
    // 4. attention 1a: partial logits (j-half x k-half split, 1024 blocks)
    attn_logits<<<dim3(NB / 2, 2, 2), 256>>>(p_qkv, p_PKT, p_Pb, rb1_b, rb2_w,
                                             rb2_b, p_w, p_w2);
    // 5. rv2^T
    transpose_kernel<<<dim3(DD / 32, DD / 32), tthr>>>(rv2_w, p_rv2T, DD, DD, DD, 0);
    // 6. attention 1b: combine partials + softmax in place
    softmax_kernel<<<NB, 256>>>(p_w, p_w2);
    // 7. attention 2a: partial T + c1 (j-split, 512 blocks)
    attn_ctx<<<dim3(NB / 2, 2), 256>>>(p_qkv, p_Pv, rv1_b, p_w, p_Tp, p_c1p);
    // 8. attention 2b: combine + c2 + residual + fused LN2
    attn_fin<<<NB / 2, 256>>>(x, p_rv2T, rv2_b, p_Tp, p_c1p, ln2_w, ln2_b, p_y, p_xn2);
    // 9. fused SwiGLU dual-GEMM
    gemm_swiglu<<<dim3((HID + 63) / 64, NB / 32), 256>>>(p_xn2, ffn_w1, ffn_b1,
                                                         ffn_w2, ffn_b2, p_h1,
                                                         NB, HID, DD);
    // 10. out = h1 @ ffn_w3^T + ffn_b3 + y   (32x32 tiles -> 128 blocks)
    gemm_t32<<<dim3(DD / 32, NB / 32), 256>>>(p_h1, ffn_w3, ffn_b3, p_y, out,
                                              NB, DD, HID);
}